// round 3
// baseline (speedup 1.0000x reference)
#include <cuda_runtime.h>
#include <cstdint>
#include <math_constants.h>

// NearestEmbed via mma.sync tf32 (3xTF32 split) + fused argmin epilogue.
// score[n,k] = ||e_k||^2 - 2 * x_n . e_k
// dot = xhi.ehi + xhi.elo + xlo.ehi  (tf32 split, fp32 accumulate)

#define D_DIM 256
#define K_DIM 1024
#define BM 128
#define BN 128
#define DC 32          // d per chunk
#define NKT (K_DIM / BN)
#define NCH (D_DIM / DC)
#define THREADS 256

#define TILE_FLOATS (DC * BM)            // 4096 floats = 16KB per operand array
#define BUF_FLOATS (4 * TILE_FLOATS)     // AH, AL, BH, BL
#define SMEM_DYN (2 * BUF_FLOATS * 4)    // 131072 bytes

__device__ float g_e2[K_DIM];
__device__ float g_xhi[64 * 256 * 1024];
__device__ float g_xlo[64 * 256 * 1024];
__device__ float g_ehi[D_DIM * K_DIM];
__device__ float g_elo[D_DIM * K_DIM];

__device__ __forceinline__ uint32_t to_tf32(float f) {
    uint32_t r;
    asm("cvt.rna.tf32.f32 %0, %1;" : "=r"(r) : "f"(f));
    return r;
}

__device__ __forceinline__ void mma8(float* c, const uint32_t* a, const uint32_t* b) {
    asm volatile(
        "mma.sync.aligned.m16n8k8.row.col.f32.tf32.tf32.f32 "
        "{%0,%1,%2,%3}, {%4,%5,%6,%7}, {%8,%9}, {%0,%1,%2,%3};"
        : "+f"(c[0]), "+f"(c[1]), "+f"(c[2]), "+f"(c[3])
        : "r"(a[0]), "r"(a[1]), "r"(a[2]), "r"(a[3]), "r"(b[0]), "r"(b[1]));
}

// swizzled word index within a 32(k) x 128(m) tile
__device__ __forceinline__ int swz(int kk, int m) {
    return kk * 128 + (m ^ ((kk & 3) << 3));
}

// ---------------- prep kernels ----------------
__global__ void e2_kernel(const float* __restrict__ emb) {
    int k = blockIdx.x * blockDim.x + threadIdx.x;
    float s = 0.f;
#pragma unroll 8
    for (int d = 0; d < D_DIM; ++d) {
        float v = emb[(size_t)d * K_DIM + k];
        s = fmaf(v, v, s);
    }
    g_e2[k] = s;
}

__global__ void cvt_kernel(const float* __restrict__ src, float* __restrict__ dhi,
                           float* __restrict__ dlo) {
    size_t i = ((size_t)blockIdx.x * blockDim.x + threadIdx.x) * 4;
    float4 v = *(const float4*)(src + i);
    float4 h, l;
    h.x = __uint_as_float(to_tf32(v.x)); l.x = __uint_as_float(to_tf32(v.x - h.x));
    h.y = __uint_as_float(to_tf32(v.y)); l.y = __uint_as_float(to_tf32(v.y - h.y));
    h.z = __uint_as_float(to_tf32(v.z)); l.z = __uint_as_float(to_tf32(v.z - h.z));
    h.w = __uint_as_float(to_tf32(v.w)); l.w = __uint_as_float(to_tf32(v.w - h.w));
    *(float4*)(dhi + i) = h;
    *(float4*)(dlo + i) = l;
}

// ---------------- main kernel ----------------
__device__ __forceinline__ void stage(float* __restrict__ buf, int dt, int k0,
                                      size_t xoff, int tid) {
    const float* xh = g_xhi + xoff;
    const float* xl = g_xlo + xoff;
#pragma unroll
    for (int i = 0; i < 4; ++i) {
        int f = tid + i * 256;
        int kk = f >> 5;
        int q = f & 31;
        int w = kk * 128 + ((4 * q) ^ ((kk & 3) << 3));
        size_t arow = (size_t)(dt + kk) * 1024 + 4 * q;
        size_t brow = (size_t)(dt + kk) * K_DIM + k0 + 4 * q;
        float4 va = *(const float4*)(xh + arow);
        float4 vb = *(const float4*)(xl + arow);
        float4 vc = *(const float4*)(g_ehi + brow);
        float4 vd = *(const float4*)(g_elo + brow);
        *(float4*)(buf + w) = va;
        *(float4*)(buf + TILE_FLOATS + w) = vb;
        *(float4*)(buf + 2 * TILE_FLOATS + w) = vc;
        *(float4*)(buf + 3 * TILE_FLOATS + w) = vd;
    }
}

__global__ __launch_bounds__(THREADS, 1)
void vq_mma_kernel(const float* __restrict__ emb, float* __restrict__ out,
                   float* __restrict__ idx_out, int has_idx) {
    extern __shared__ float sm[];
    __shared__ float e2s[K_DIM];
    __shared__ float redv[BM][2];
    __shared__ int redi[BM][2];
    __shared__ int idx_s[BM];

    const int tid = threadIdx.x;
    const int wid = tid >> 5;
    const int lane = tid & 31;
    const int gid = lane >> 2;
    const int tig = lane & 3;
    const int mbw = (wid >> 1) * 32;  // warp M offset (0..96)
    const int nbw = (wid & 1) * 64;   // warp N offset (0/64)
    const int sw = tig << 3;

    const int n0 = blockIdx.x * BM;
    const int b = n0 >> 10;
    const int hw0 = n0 & 1023;
    const size_t xoff = (size_t)b * D_DIM * 1024 + hw0;

    for (int i = tid; i < K_DIM; i += THREADS) e2s[i] = g_e2[i];

    float best[4];
    int bidx[4];
#pragma unroll
    for (int s = 0; s < 4; ++s) { best[s] = CUDART_INF_F; bidx[s] = 0; }

    for (int kt = 0; kt < NKT; ++kt) {
        const int k0 = kt * BN;
        float acc[2][8][4];
#pragma unroll
        for (int mt = 0; mt < 2; ++mt)
#pragma unroll
            for (int nt = 0; nt < 8; ++nt)
#pragma unroll
                for (int j = 0; j < 4; ++j) acc[mt][nt][j] = 0.f;

        __syncthreads();
        stage(sm, 0, k0, xoff, tid);
        __syncthreads();

        for (int ch = 0; ch < NCH; ++ch) {
            float* cur = sm + (ch & 1) * BUF_FLOATS;
            if (ch + 1 < NCH) stage(sm + ((ch + 1) & 1) * BUF_FLOATS, (ch + 1) * DC, k0, xoff, tid);

            const float* AH = cur;
            const float* AL = cur + TILE_FLOATS;
            const float* BH = cur + 2 * TILE_FLOATS;
            const float* BL = cur + 3 * TILE_FLOATS;

            for (int g = 0; g < 4; ++g) {
                const int kkA = g * 8 + tig;
                uint32_t ahi[2][4], alo[2][4];
#pragma unroll
                for (int mt = 0; mt < 2; ++mt) {
                    const int M0 = mbw + mt * 16 + gid;
                    int w0 = kkA * 128 + (M0 ^ sw);
                    int w1 = kkA * 128 + ((M0 + 8) ^ sw);
                    int w2 = (kkA + 4) * 128 + (M0 ^ sw);
                    int w3 = (kkA + 4) * 128 + ((M0 + 8) ^ sw);
                    ahi[mt][0] = __float_as_uint(AH[w0]);
                    ahi[mt][1] = __float_as_uint(AH[w1]);
                    ahi[mt][2] = __float_as_uint(AH[w2]);
                    ahi[mt][3] = __float_as_uint(AH[w3]);
                    alo[mt][0] = __float_as_uint(AL[w0]);
                    alo[mt][1] = __float_as_uint(AL[w1]);
                    alo[mt][2] = __float_as_uint(AL[w2]);
                    alo[mt][3] = __float_as_uint(AL[w3]);
                }
#pragma unroll
                for (int nt = 0; nt < 8; ++nt) {
                    const int n = nbw + nt * 8 + gid;
                    int w0 = kkA * 128 + (n ^ sw);
                    int w1 = (kkA + 4) * 128 + (n ^ sw);
                    uint32_t bh[2], bl[2];
                    bh[0] = __float_as_uint(BH[w0]);
                    bh[1] = __float_as_uint(BH[w1]);
                    bl[0] = __float_as_uint(BL[w0]);
                    bl[1] = __float_as_uint(BL[w1]);
                    mma8(acc[0][nt], ahi[0], bh);
                    mma8(acc[0][nt], ahi[0], bl);
                    mma8(acc[0][nt], alo[0], bh);
                    mma8(acc[1][nt], ahi[1], bh);
                    mma8(acc[1][nt], ahi[1], bl);
                    mma8(acc[1][nt], alo[1], bh);
                }
            }
            __syncthreads();
        }

        // fused argmin epilogue for this 128-code tile
#pragma unroll
        for (int mt = 0; mt < 2; ++mt) {
#pragma unroll
            for (int nt = 0; nt < 8; ++nt) {
                const int kc = k0 + nbw + nt * 8 + 2 * tig;
                const float e20 = e2s[kc], e21 = e2s[kc + 1];
                float s0 = fmaf(-2.f, acc[mt][nt][0], e20);
                float s1 = fmaf(-2.f, acc[mt][nt][1], e21);
                float s2 = fmaf(-2.f, acc[mt][nt][2], e20);
                float s3 = fmaf(-2.f, acc[mt][nt][3], e21);
                if (s0 < best[2 * mt]) { best[2 * mt] = s0; bidx[2 * mt] = kc; }
                if (s1 < best[2 * mt]) { best[2 * mt] = s1; bidx[2 * mt] = kc + 1; }
                if (s2 < best[2 * mt + 1]) { best[2 * mt + 1] = s2; bidx[2 * mt + 1] = kc; }
                if (s3 < best[2 * mt + 1]) { best[2 * mt + 1] = s3; bidx[2 * mt + 1] = kc + 1; }
            }
        }
    }

    // reduce across the 4 lanes of each quad (same rows, different cols)
#pragma unroll
    for (int s = 0; s < 4; ++s) {
        float v = best[s];
        int ix = bidx[s];
#pragma unroll
        for (int off = 1; off <= 2; off <<= 1) {
            float v2 = __shfl_xor_sync(0xFFFFFFFFu, v, off);
            int i2 = __shfl_xor_sync(0xFFFFFFFFu, ix, off);
            if (v2 < v || (v2 == v && i2 < ix)) { v = v2; ix = i2; }
        }
        if (tig == 0) {
            int row = mbw + (s >> 1) * 16 + gid + (s & 1) * 8;
            redv[row][wid & 1] = v;
            redi[row][wid & 1] = ix;
        }
    }
    __syncthreads();
    if (tid < BM) {
        float v0 = redv[tid][0], v1 = redv[tid][1];
        int i0 = redi[tid][0], i1 = redi[tid][1];
        int bi = (v1 < v0 || (v1 == v0 && i1 < i0)) ? i1 : i0;
        idx_s[tid] = bi;
        if (has_idx) idx_out[n0 + tid] = (float)bi;
    }
    __syncthreads();

    // gather nearest code (exact fp32), scatter to (B,D,H,W)
    for (int r = tid; r < D_DIM * BM; r += THREADS) {
        int d = r >> 7;
        int m = r & (BM - 1);
        out[((size_t)b * D_DIM + d) * 1024 + hw0 + m] = emb[(size_t)d * K_DIM + idx_s[m]];
    }
}

extern "C" void kernel_launch(void* const* d_in, const int* in_sizes, int n_in,
                              void* d_out, int out_size) {
    const float* x = (const float*)d_in[0];    // (64,256,32,32)
    const float* emb = (const float*)d_in[1];  // (256,1024)
    float* out = (float*)d_out;

    const int n_img = 64 * 256 * 32 * 32;
    const int n_lat = 64 * 32 * 32;
    float* idx_out = nullptr;
    int has_idx = 0;
    if (out_size >= n_img + n_lat) {
        idx_out = out + n_img;
        has_idx = 1;
    }

    cudaFuncSetAttribute(vq_mma_kernel, cudaFuncAttributeMaxDynamicSharedMemorySize, SMEM_DYN);

    float* xhi; cudaGetSymbolAddress((void**)&xhi, g_xhi);
    float* xlo; cudaGetSymbolAddress((void**)&xlo, g_xlo);
    float* ehi; cudaGetSymbolAddress((void**)&ehi, g_ehi);
    float* elo; cudaGetSymbolAddress((void**)&elo, g_elo);

    e2_kernel<<<4, 256>>>(emb);
    cvt_kernel<<<n_img / 1024, 256>>>(x, xhi, xlo);
    cvt_kernel<<<(D_DIM * K_DIM) / 1024, 256>>>(emb, ehi, elo);
    vq_mma_kernel<<<512, 256, SMEM_DYN>>>(emb, out, idx_out, has_idx);
}

// round 4
// speedup vs baseline: 1.0438x; 1.0438x over previous
#include <cuda_runtime.h>
#include <cstdint>
#include <math_constants.h>

// NearestEmbed via mma.sync tf32 (3xTF32 split) + fused argmin epilogue.
// score[n,k] = ||e_k||^2 - 2 * x_n . e_k
// dot = xhi.ehi + xhi.elo + xlo.ehi  (tf32 split, fp32 accumulate)
// R4: 512 threads / 16 warps, warp tile 32x32 -> 4 warps/SMSP (was 2).

#define D_DIM 256
#define K_DIM 1024
#define BM 128
#define BN 128
#define DC 32          // d per chunk
#define NKT (K_DIM / BN)
#define NCH (D_DIM / DC)
#define THREADS 512

#define TILE_FLOATS (DC * BM)            // 4096 floats = 16KB per operand array
#define BUF_FLOATS (4 * TILE_FLOATS)     // AH, AL, BH, BL
#define SMEM_DYN (2 * BUF_FLOATS * 4)    // 131072 bytes

__device__ float g_e2[K_DIM];
__device__ float g_xhi[64 * 256 * 1024];
__device__ float g_xlo[64 * 256 * 1024];
__device__ float g_ehi[D_DIM * K_DIM];
__device__ float g_elo[D_DIM * K_DIM];

__device__ __forceinline__ uint32_t to_tf32(float f) {
    uint32_t r;
    asm("cvt.rna.tf32.f32 %0, %1;" : "=r"(r) : "f"(f));
    return r;
}

__device__ __forceinline__ void mma8(float* c, const uint32_t* a, const uint32_t* b) {
    asm volatile(
        "mma.sync.aligned.m16n8k8.row.col.f32.tf32.tf32.f32 "
        "{%0,%1,%2,%3}, {%4,%5,%6,%7}, {%8,%9}, {%0,%1,%2,%3};"
        : "+f"(c[0]), "+f"(c[1]), "+f"(c[2]), "+f"(c[3])
        : "r"(a[0]), "r"(a[1]), "r"(a[2]), "r"(a[3]), "r"(b[0]), "r"(b[1]));
}

// ---------------- prep kernels ----------------
__global__ void e2_kernel(const float* __restrict__ emb) {
    int k = blockIdx.x * blockDim.x + threadIdx.x;
    float s = 0.f;
#pragma unroll 8
    for (int d = 0; d < D_DIM; ++d) {
        float v = emb[(size_t)d * K_DIM + k];
        s = fmaf(v, v, s);
    }
    g_e2[k] = s;
}

__global__ void cvt_kernel(const float* __restrict__ src, float* __restrict__ dhi,
                           float* __restrict__ dlo) {
    size_t i = ((size_t)blockIdx.x * blockDim.x + threadIdx.x) * 4;
    float4 v = *(const float4*)(src + i);
    float4 h, l;
    h.x = __uint_as_float(to_tf32(v.x)); l.x = __uint_as_float(to_tf32(v.x - h.x));
    h.y = __uint_as_float(to_tf32(v.y)); l.y = __uint_as_float(to_tf32(v.y - h.y));
    h.z = __uint_as_float(to_tf32(v.z)); l.z = __uint_as_float(to_tf32(v.z - h.z));
    h.w = __uint_as_float(to_tf32(v.w)); l.w = __uint_as_float(to_tf32(v.w - h.w));
    *(float4*)(dhi + i) = h;
    *(float4*)(dlo + i) = l;
}

// ---------------- main kernel ----------------
__device__ __forceinline__ void stage(float* __restrict__ buf, int dt, int k0,
                                      size_t xoff, int tid) {
    const float* xh = g_xhi + xoff;
    const float* xl = g_xlo + xoff;
#pragma unroll
    for (int i = 0; i < 2; ++i) {
        int f = tid + i * THREADS;
        int kk = f >> 5;
        int q = f & 31;
        int w = kk * 128 + ((4 * q) ^ ((kk & 3) << 3));
        size_t arow = (size_t)(dt + kk) * 1024 + 4 * q;
        size_t brow = (size_t)(dt + kk) * K_DIM + k0 + 4 * q;
        float4 va = *(const float4*)(xh + arow);
        float4 vb = *(const float4*)(xl + arow);
        float4 vc = *(const float4*)(g_ehi + brow);
        float4 vd = *(const float4*)(g_elo + brow);
        *(float4*)(buf + w) = va;
        *(float4*)(buf + TILE_FLOATS + w) = vb;
        *(float4*)(buf + 2 * TILE_FLOATS + w) = vc;
        *(float4*)(buf + 3 * TILE_FLOATS + w) = vd;
    }
}

__global__ __launch_bounds__(THREADS, 1)
void vq_mma_kernel(const float* __restrict__ emb, float* __restrict__ out,
                   float* __restrict__ idx_out, int has_idx) {
    extern __shared__ float sm[];
    __shared__ float e2s[K_DIM];
    __shared__ float redv[BM][4];
    __shared__ int redi[BM][4];
    __shared__ int idx_s[BM];

    const int tid = threadIdx.x;
    const int wid = tid >> 5;
    const int lane = tid & 31;
    const int gid = lane >> 2;
    const int tig = lane & 3;
    const int wm = wid >> 2;          // 0..3
    const int wn = wid & 3;           // 0..3
    const int mbw = wm * 32;          // warp M offset
    const int nbw = wn * 32;          // warp N offset
    const int sw = tig << 3;

    const int n0 = blockIdx.x * BM;
    const int b = n0 >> 10;
    const int hw0 = n0 & 1023;
    const size_t xoff = (size_t)b * D_DIM * 1024 + hw0;

    for (int i = tid; i < K_DIM; i += THREADS) e2s[i] = g_e2[i];

    float best[4];
    int bidx[4];
#pragma unroll
    for (int s = 0; s < 4; ++s) { best[s] = CUDART_INF_F; bidx[s] = 0; }

    for (int kt = 0; kt < NKT; ++kt) {
        const int k0 = kt * BN;
        float acc[2][4][4];
#pragma unroll
        for (int mt = 0; mt < 2; ++mt)
#pragma unroll
            for (int nt = 0; nt < 4; ++nt)
#pragma unroll
                for (int j = 0; j < 4; ++j) acc[mt][nt][j] = 0.f;

        __syncthreads();
        stage(sm, 0, k0, xoff, tid);
        __syncthreads();

        for (int ch = 0; ch < NCH; ++ch) {
            float* cur = sm + (ch & 1) * BUF_FLOATS;
            if (ch + 1 < NCH) stage(sm + ((ch + 1) & 1) * BUF_FLOATS, (ch + 1) * DC, k0, xoff, tid);

            const float* AH = cur;
            const float* AL = cur + TILE_FLOATS;
            const float* BH = cur + 2 * TILE_FLOATS;
            const float* BL = cur + 3 * TILE_FLOATS;

#pragma unroll
            for (int g = 0; g < 4; ++g) {
                const int kkA = g * 8 + tig;
                uint32_t ahi[2][4], alo[2][4];
#pragma unroll
                for (int mt = 0; mt < 2; ++mt) {
                    const int M0 = mbw + mt * 16 + gid;
                    int w0 = kkA * 128 + (M0 ^ sw);
                    int w1 = kkA * 128 + ((M0 + 8) ^ sw);
                    int w2 = (kkA + 4) * 128 + (M0 ^ sw);
                    int w3 = (kkA + 4) * 128 + ((M0 + 8) ^ sw);
                    ahi[mt][0] = __float_as_uint(AH[w0]);
                    ahi[mt][1] = __float_as_uint(AH[w1]);
                    ahi[mt][2] = __float_as_uint(AH[w2]);
                    ahi[mt][3] = __float_as_uint(AH[w3]);
                    alo[mt][0] = __float_as_uint(AL[w0]);
                    alo[mt][1] = __float_as_uint(AL[w1]);
                    alo[mt][2] = __float_as_uint(AL[w2]);
                    alo[mt][3] = __float_as_uint(AL[w3]);
                }
#pragma unroll
                for (int nt = 0; nt < 4; ++nt) {
                    const int n = nbw + nt * 8 + gid;
                    int w0 = kkA * 128 + (n ^ sw);
                    int w1 = (kkA + 4) * 128 + (n ^ sw);
                    uint32_t bh[2], bl[2];
                    bh[0] = __float_as_uint(BH[w0]);
                    bh[1] = __float_as_uint(BH[w1]);
                    bl[0] = __float_as_uint(BL[w0]);
                    bl[1] = __float_as_uint(BL[w1]);
                    mma8(acc[0][nt], ahi[0], bh);
                    mma8(acc[0][nt], ahi[0], bl);
                    mma8(acc[0][nt], alo[0], bh);
                    mma8(acc[1][nt], ahi[1], bh);
                    mma8(acc[1][nt], ahi[1], bl);
                    mma8(acc[1][nt], alo[1], bh);
                }
            }
            __syncthreads();
        }

        // fused argmin epilogue for this 128-code tile
#pragma unroll
        for (int mt = 0; mt < 2; ++mt) {
#pragma unroll
            for (int nt = 0; nt < 4; ++nt) {
                const int kc = k0 + nbw + nt * 8 + 2 * tig;
                const float e20 = e2s[kc], e21 = e2s[kc + 1];
                float s0 = fmaf(-2.f, acc[mt][nt][0], e20);
                float s1 = fmaf(-2.f, acc[mt][nt][1], e21);
                float s2 = fmaf(-2.f, acc[mt][nt][2], e20);
                float s3 = fmaf(-2.f, acc[mt][nt][3], e21);
                if (s0 < best[2 * mt]) { best[2 * mt] = s0; bidx[2 * mt] = kc; }
                if (s1 < best[2 * mt]) { best[2 * mt] = s1; bidx[2 * mt] = kc + 1; }
                if (s2 < best[2 * mt + 1]) { best[2 * mt + 1] = s2; bidx[2 * mt + 1] = kc; }
                if (s3 < best[2 * mt + 1]) { best[2 * mt + 1] = s3; bidx[2 * mt + 1] = kc + 1; }
            }
        }
    }

    // reduce across the 4 lanes of each quad (same rows, different cols)
#pragma unroll
    for (int s = 0; s < 4; ++s) {
        float v = best[s];
        int ix = bidx[s];
#pragma unroll
        for (int off = 1; off <= 2; off <<= 1) {
            float v2 = __shfl_xor_sync(0xFFFFFFFFu, v, off);
            int i2 = __shfl_xor_sync(0xFFFFFFFFu, ix, off);
            if (v2 < v || (v2 == v && i2 < ix)) { v = v2; ix = i2; }
        }
        if (tig == 0) {
            int row = mbw + (s >> 1) * 16 + gid + (s & 1) * 8;
            redv[row][wn] = v;
            redi[row][wn] = ix;
        }
    }
    __syncthreads();
    if (tid < BM) {
        float bv = redv[tid][0];
        int bi = redi[tid][0];
#pragma unroll
        for (int t = 1; t < 4; ++t) {
            float v = redv[tid][t];
            int id = redi[tid][t];
            if (v < bv || (v == bv && id < bi)) { bv = v; bi = id; }
        }
        idx_s[tid] = bi;
        if (has_idx) idx_out[n0 + tid] = (float)bi;
    }
    __syncthreads();

    // gather nearest code (exact fp32), scatter to (B,D,H,W)
    for (int r = tid; r < D_DIM * BM; r += THREADS) {
        int d = r >> 7;
        int m = r & (BM - 1);
        out[((size_t)b * D_DIM + d) * 1024 + hw0 + m] = emb[(size_t)d * K_DIM + idx_s[m]];
    }
}

extern "C" void kernel_launch(void* const* d_in, const int* in_sizes, int n_in,
                              void* d_out, int out_size) {
    const float* x = (const float*)d_in[0];    // (64,256,32,32)
    const float* emb = (const float*)d_in[1];  // (256,1024)
    float* out = (float*)d_out;

    const int n_img = 64 * 256 * 32 * 32;
    const int n_lat = 64 * 32 * 32;
    float* idx_out = nullptr;
    int has_idx = 0;
    if (out_size >= n_img + n_lat) {
        idx_out = out + n_img;
        has_idx = 1;
    }

    cudaFuncSetAttribute(vq_mma_kernel, cudaFuncAttributeMaxDynamicSharedMemorySize, SMEM_DYN);

    float* xhi; cudaGetSymbolAddress((void**)&xhi, g_xhi);
    float* xlo; cudaGetSymbolAddress((void**)&xlo, g_xlo);
    float* ehi; cudaGetSymbolAddress((void**)&ehi, g_ehi);
    float* elo; cudaGetSymbolAddress((void**)&elo, g_elo);

    e2_kernel<<<4, 256>>>(emb);
    cvt_kernel<<<n_img / 1024, 256>>>(x, xhi, xlo);
    cvt_kernel<<<(D_DIM * K_DIM) / 1024, 256>>>(emb, ehi, elo);
    vq_mma_kernel<<<512, THREADS, SMEM_DYN>>>(emb, out, idx_out, has_idx);
}